// round 1
// baseline (speedup 1.0000x reference)
#include <cuda_runtime.h>

// Problem constants
#define HH 384
#define WW 384
#define NBATCH 16
#define GROUPS 5
#define ICG 4      // in channels per group  (20/5)
#define OCG 8      // out channels per group (40/5)
#define KS 5       // padded kernel size
#define PAD 2
#define TILE 32
#define HALO 36    // TILE + KS - 1

// Synthesized filters: [group][ic][tap(25)][oc(8)]  (oc contiguous -> f32x2 pairs)
__device__ float g_w[GROUPS * ICG * 25 * OCG];

// ---------------------------------------------------------------------------
// Kernel 1: synthesize Gaussian-Hermite filters from alphas + scales.
// One thread per (scale, ic, oc) triple: 5*4*8 = 160 threads.
// ---------------------------------------------------------------------------
__global__ void make_filters_kernel(const float* __restrict__ alphas,
                                    const float* __restrict__ scales) {
    int tid = threadIdx.x;
    if (tid >= GROUPS * ICG * OCG) return;
    int s  = tid / (ICG * OCG);
    int ic = (tid / OCG) % ICG;
    int oc = tid % OCG;

    const int FS_[5] = {1, 1, 1, 2, 2};   // static half-supports (from SIGMA0)
    float mn = 0.2f * s;
    float mx = mn + 0.2f;
    float sigma = (mx - mn) * 0.5f * tanhf(scales[s]) + (mn + mx) * 0.5f;
    int fs  = FS_[s];
    int len = 2 * fs + 1;

    float g[5];
    float gsum = 0.f;
    for (int k = 0; k < len; k++) {
        float x = (float)(k - fs);
        g[k] = expf(-(x * x) / (2.f * sigma * sigma));
        gsum += g[k];
    }
    float inv = 1.f / gsum;
    const float SQRT2 = 1.4142135623730951f;
    float c1 = -1.f / (sigma * SQRT2);

    float d0[5], d1[5], d2[5];
    for (int k = 0; k < len; k++) {
        float x  = (float)(k - fs);
        float u  = x / (sigma * SQRT2);
        float gg = g[k] * inv;
        d0[k] = gg;
        d1[k] = c1 * (2.f * u) * gg;                 // (-1/(s*sqrt2))^1 * H1 * g
        d2[k] = c1 * c1 * (4.f * u * u - 2.f) * gg;  // (-1/(s*sqrt2))^2 * H2 * g
    }

    // alphas layout: [s][n(6)][ic(4)][oc(8)]
    float a[6];
    for (int n = 0; n < 6; n++)
        a[n] = alphas[((s * 6 + n) * ICG + ic) * OCG + oc];

    int p = (KS - len) / 2;   // centered zero pad
    for (int ky = 0; ky < KS; ky++) {
        for (int kx = 0; kx < KS; kx++) {
            float v = 0.f;
            int yy = ky - p, xx = kx - p;
            if (yy >= 0 && yy < len && xx >= 0 && xx < len) {
                // basis order: (i,j) = (0,0),(0,1),(0,2),(1,0),(1,1),(2,0)
                v = a[0] * d0[yy] * d0[xx]
                  + a[1] * d0[yy] * d1[xx]
                  + a[2] * d0[yy] * d2[xx]
                  + a[3] * d1[yy] * d0[xx]
                  + a[4] * d1[yy] * d1[xx]
                  + a[5] * d2[yy] * d0[xx];
            }
            g_w[((s * ICG + ic) * 25 + ky * KS + kx) * OCG + oc] = v;
        }
    }
}

// ---------------------------------------------------------------------------
// Packed fp32x2 helpers (sm_103a FFMA2 path)
// ---------------------------------------------------------------------------
__device__ __forceinline__ unsigned long long pk2(float v) {
    unsigned long long r;
    asm("mov.b64 %0, {%1, %1};" : "=l"(r) : "r"(__float_as_uint(v)));
    return r;
}
__device__ __forceinline__ unsigned long long fma2(unsigned long long a,
                                                   unsigned long long b,
                                                   unsigned long long c) {
    unsigned long long d;
    asm("fma.rn.f32x2 %0, %1, %2, %3;" : "=l"(d) : "l"(a), "l"(b), "l"(c));
    return d;
}

// ---------------------------------------------------------------------------
// Kernel 2: direct grouped conv. Block = one (n, g, 32x32 tile).
// Each thread: 8 oc x 4 px, oc paired into f32x2 accumulators.
// ---------------------------------------------------------------------------
__global__ __launch_bounds__(256)
void conv_kernel(const float* __restrict__ in, float* __restrict__ out) {
    __shared__ __align__(16) float s_in[ICG][HALO][HALO];
    __shared__ __align__(16) float s_w[ICG][25][OCG];

    int bx = blockIdx.x, by = blockIdx.y;
    int n = blockIdx.z / GROUPS;
    int g = blockIdx.z % GROUPS;
    int tid = threadIdx.x;

    // Load this group's weights (800 floats)
    for (int i = tid; i < ICG * 25 * OCG; i += 256)
        ((float*)s_w)[i] = g_w[g * (ICG * 25 * OCG) + i];

    // Load haloed input tile (4 x 36 x 36)
    int y0 = by * TILE - PAD, x0 = bx * TILE - PAD;
    const float* inb = in + ((size_t)n * (GROUPS * ICG) + g * ICG) * (HH * WW);
    for (int i = tid; i < ICG * HALO * HALO; i += 256) {
        int ic  = i / (HALO * HALO);
        int rem = i % (HALO * HALO);
        int yy  = rem / HALO, xx = rem % HALO;
        int gy = y0 + yy, gx = x0 + xx;
        float v = 0.f;
        if (gy >= 0 && gy < HH && gx >= 0 && gx < WW)
            v = inb[(size_t)ic * HH * WW + (size_t)gy * WW + gx];
        ((float*)s_in)[i] = v;
    }
    __syncthreads();

    int r = tid >> 3;          // 0..31 (row in tile)
    int c = (tid & 7) << 2;    // 0,4,..,28 (col of 4-px strip)

    // acc[px*4 + p] = f32x2 pair for (oc=2p, oc=2p+1) at pixel px
    unsigned long long acc[16];
#pragma unroll
    for (int i = 0; i < 16; i++) acc[i] = 0ull;

    for (int ic = 0; ic < ICG; ic++) {
        const float* wbase = &s_w[ic][0][0];
#pragma unroll
        for (int ky = 0; ky < KS; ky++) {
            const float* irow = &s_in[ic][r + ky][c];
            float4 ra = *(const float4*)irow;
            float4 rb = *(const float4*)(irow + 4);
            unsigned long long v2[8];
            v2[0] = pk2(ra.x); v2[1] = pk2(ra.y); v2[2] = pk2(ra.z); v2[3] = pk2(ra.w);
            v2[4] = pk2(rb.x); v2[5] = pk2(rb.y); v2[6] = pk2(rb.z); v2[7] = pk2(rb.w);
#pragma unroll
            for (int kx = 0; kx < KS; kx++) {
                const ulonglong2* wp = (const ulonglong2*)&wbase[(ky * KS + kx) * OCG];
                ulonglong2 wA = wp[0];   // pairs (oc0,oc1), (oc2,oc3)
                ulonglong2 wB = wp[1];   // pairs (oc4,oc5), (oc6,oc7)
#pragma unroll
                for (int px = 0; px < 4; px++) {
                    unsigned long long v = v2[kx + px];
                    acc[px * 4 + 0] = fma2(v, wA.x, acc[px * 4 + 0]);
                    acc[px * 4 + 1] = fma2(v, wA.y, acc[px * 4 + 1]);
                    acc[px * 4 + 2] = fma2(v, wB.x, acc[px * 4 + 2]);
                    acc[px * 4 + 3] = fma2(v, wB.y, acc[px * 4 + 3]);
                }
            }
        }
    }

    // Write 8 oc x 4 px (float4 per oc row)
    int gy = by * TILE + r, gx = bx * TILE + c;
    float* ob = out + (((size_t)n * (GROUPS * OCG) + g * OCG) * HH + gy) * (size_t)WW + gx;
#pragma unroll
    for (int p = 0; p < 4; p++) {
        float4 lo4, hi4;
        lo4.x = __uint_as_float((unsigned)(acc[0 * 4 + p]));
        lo4.y = __uint_as_float((unsigned)(acc[1 * 4 + p]));
        lo4.z = __uint_as_float((unsigned)(acc[2 * 4 + p]));
        lo4.w = __uint_as_float((unsigned)(acc[3 * 4 + p]));
        hi4.x = __uint_as_float((unsigned)(acc[0 * 4 + p] >> 32));
        hi4.y = __uint_as_float((unsigned)(acc[1 * 4 + p] >> 32));
        hi4.z = __uint_as_float((unsigned)(acc[2 * 4 + p] >> 32));
        hi4.w = __uint_as_float((unsigned)(acc[3 * 4 + p] >> 32));
        *(float4*)(ob + (size_t)(2 * p)     * HH * WW) = lo4;
        *(float4*)(ob + (size_t)(2 * p + 1) * HH * WW) = hi4;
    }
}

// ---------------------------------------------------------------------------
extern "C" void kernel_launch(void* const* d_in, const int* in_sizes, int n_in,
                              void* d_out, int out_size) {
    const float* data   = (const float*)d_in[0];  // [16,20,384,384]
    const float* alphas = (const float*)d_in[1];  // [5,6,4,8]
    const float* scales = (const float*)d_in[2];  // [5]
    float* out = (float*)d_out;                   // [16,40,384,384]

    make_filters_kernel<<<1, 256>>>(alphas, scales);

    dim3 grid(WW / TILE, HH / TILE, NBATCH * GROUPS);  // 12 x 12 x 80
    conv_kernel<<<grid, 256>>>(data, out);
}

// round 2
// speedup vs baseline: 1.3128x; 1.3128x over previous
#include <cuda_runtime.h>

#define HH 384
#define WW 384
#define NBATCH 16
#define GROUPS 5
#define ICG 4      // in channels per group
#define OCG 8      // out channels per group
#define KS 5
#define PAD 2
#define TILE 32
#define HALO 36
#define VSTRIDE 40 // padded x-stride of s_v (16B multiple)

// Dup-packed (v,v) 1D Gaussian-derivative filters: [group][deriv 0..2][tap 0..4]
__device__ unsigned long long g_d2[GROUPS][3][KS];

// ---------------------------------------------------------------------------
// Kernel 1: synthesize the three 1-D derivative filters per scale.
// ---------------------------------------------------------------------------
__global__ void make_filters_kernel(const float* __restrict__ scales) {
    int s = threadIdx.x;
    if (s >= GROUPS) return;
    const int FS_[5] = {1, 1, 1, 2, 2};
    float mn = 0.2f * s, mx = mn + 0.2f;
    float sigma = (mx - mn) * 0.5f * tanhf(scales[s]) + (mn + mx) * 0.5f;
    int fs = FS_[s], len = 2 * fs + 1;

    float g[5]; float gsum = 0.f;
    for (int k = 0; k < len; k++) {
        float x = (float)(k - fs);
        g[k] = expf(-(x * x) / (2.f * sigma * sigma));
        gsum += g[k];
    }
    float inv = 1.f / gsum;
    const float SQRT2 = 1.4142135623730951f;
    float c1 = -1.f / (sigma * SQRT2);

    float d[3][5];
    for (int i = 0; i < 3; i++)
        for (int k = 0; k < 5; k++) d[i][k] = 0.f;
    int p = (KS - len) / 2;
    for (int k = 0; k < len; k++) {
        float x = (float)(k - fs);
        float u = x / (sigma * SQRT2);
        float gg = g[k] * inv;
        d[0][p + k] = gg;
        d[1][p + k] = c1 * (2.f * u) * gg;
        d[2][p + k] = c1 * c1 * (4.f * u * u - 2.f) * gg;
    }
    for (int i = 0; i < 3; i++)
        for (int k = 0; k < 5; k++) {
            unsigned ui = __float_as_uint(d[i][k]);
            g_d2[s][i][k] = ((unsigned long long)ui << 32) | ui;
        }
}

// ---------------------------------------------------------------------------
// f32x2 helpers
// ---------------------------------------------------------------------------
__device__ __forceinline__ unsigned long long fma2(unsigned long long a,
                                                   unsigned long long b,
                                                   unsigned long long c) {
    unsigned long long d;
    asm("fma.rn.f32x2 %0, %1, %2, %3;" : "=l"(d) : "l"(a), "l"(b), "l"(c));
    return d;
}
__device__ __forceinline__ unsigned long long pk2f(float a, float b) {
    unsigned long long r;
    asm("mov.b64 %0, {%1, %2};" : "=l"(r)
        : "r"(__float_as_uint(a)), "r"(__float_as_uint(b)));
    return r;
}
__device__ __forceinline__ void upk2(unsigned long long v, float& a, float& b) {
    unsigned x, y;
    asm("mov.b64 {%0, %1}, %2;" : "=r"(x), "=r"(y) : "l"(v));
    a = __uint_as_float(x); b = __uint_as_float(y);
}

// ---------------------------------------------------------------------------
// Kernel 2: fused separable conv.  Block = (n, g, 32x32 tile), 256 threads.
// Per ic: vertical 1-D pass into s_v, then horizontal + pointwise accumulate.
// ---------------------------------------------------------------------------
__global__ __launch_bounds__(256, 3)
void conv_kernel(const float* __restrict__ in,
                 const float* __restrict__ alphas,
                 float* __restrict__ out) {
    __shared__ __align__(16) float s_in[ICG][HALO][HALO];
    __shared__ __align__(16) float s_v[3][TILE][VSTRIDE];
    __shared__ __align__(16) float s_a[6][ICG][OCG];          // alphas for this group
    __shared__ __align__(16) unsigned long long s_d2[3][KS];  // dup-packed 1D filters

    int bx = blockIdx.x, by = blockIdx.y;
    int n = blockIdx.z / GROUPS;
    int g = blockIdx.z % GROUPS;
    int tid = threadIdx.x;

    // weights into smem
    if (tid < 6 * ICG * OCG)
        ((float*)s_a)[tid] = alphas[g * (6 * ICG * OCG) + tid];
    if (tid >= 224 && tid < 224 + 15)
        ((unsigned long long*)s_d2)[tid - 224] =
            ((const unsigned long long*)g_d2)[g * 15 + (tid - 224)];

    // haloed input tile (4 x 36 x 36)
    int y0 = by * TILE - PAD, x0 = bx * TILE - PAD;
    const float* inb = in + ((size_t)n * (GROUPS * ICG) + g * ICG) * (HH * WW);
    for (int i = tid; i < ICG * HALO * HALO; i += 256) {
        int ic  = i / (HALO * HALO);
        int rem = i % (HALO * HALO);
        int yy  = rem / HALO, xx = rem % HALO;
        int gy = y0 + yy, gx = x0 + xx;
        float v = 0.f;
        if (gy >= 0 && gy < HH && gx >= 0 && gx < WW)
            v = inb[(size_t)ic * HH * WW + (size_t)gy * WW + gx];
        ((float*)s_in)[i] = v;
    }
    __syncthreads();

    int r = tid >> 3;          // output row in tile
    int c = (tid & 7) << 2;    // output col (4-px strip)

    // acc[ocp*4+px]: f32x2 = (oc=2*ocp, oc=2*ocp+1) at pixel px
    unsigned long long acc[16];
#pragma unroll
    for (int k = 0; k < 16; k++) acc[k] = 0ull;

    const unsigned long long* d2f = (const unsigned long long*)s_d2;

    for (int ic = 0; ic < ICG; ic++) {
        if (ic) __syncthreads();   // previous s_v fully consumed

        // ---- vertical pass: v_i[y][x] = sum_dy d_i[dy] * in[y+dy][x] ----
        // 576 (y, xpair) slots over 32 rows x 18 aligned x-pairs
        for (int slot = tid; slot < TILE * 18; slot += 256) {
            int y = slot / 18;
            int xp = slot - y * 18;
            const float* col = &s_in[ic][y][2 * xp];
            unsigned long long in2[5];
#pragma unroll
            for (int dy = 0; dy < 5; dy++)
                in2[dy] = *(const unsigned long long*)(col + dy * HALO);
#pragma unroll
            for (int i = 0; i < 3; i++) {
                unsigned long long v = 0ull;
#pragma unroll
                for (int dy = 0; dy < 5; dy++)
                    v = fma2(in2[dy], d2f[i * 5 + dy], v);
                *(unsigned long long*)&s_v[i][y][2 * xp] = v;
            }
        }
        __syncthreads();

        // ---- horizontal + pointwise ----
#pragma unroll
        for (int i = 0; i < 3; i++) {
            const float* vp = &s_v[i][r][c];
            float4 fa = *(const float4*)vp;
            float4 fb = *(const float4*)(vp + 4);
            float f[8] = {fa.x, fa.y, fa.z, fa.w, fb.x, fb.y, fb.z, fb.w};
            unsigned long long pr[7];
#pragma unroll
            for (int k = 0; k < 7; k++) pr[k] = pk2f(f[k], f[k + 1]);
#pragma unroll
            for (int j = 0; j <= 2 - i; j++) {
                const int ij = (i == 0) ? j : ((i == 1) ? 3 + j : 5);
                unsigned long long h0 = 0ull, h1 = 0ull;
#pragma unroll
                for (int dx = 0; dx < 5; dx++) {
                    unsigned long long dd = d2f[j * 5 + dx];
                    h0 = fma2(pr[dx], dd, h0);
                    h1 = fma2(pr[dx + 2], dd, h1);
                }
                float ha, hb, hc, he;
                upk2(h0, ha, hb);
                upk2(h1, hc, he);
                unsigned long long hd[4] = {pk2f(ha, ha), pk2f(hb, hb),
                                            pk2f(hc, hc), pk2f(he, he)};
                const unsigned long long* ap =
                    (const unsigned long long*)&s_a[ij][ic][0];
#pragma unroll
                for (int ocp = 0; ocp < 4; ocp++) {
                    unsigned long long a2 = ap[ocp];
#pragma unroll
                    for (int px = 0; px < 4; px++)
                        acc[ocp * 4 + px] = fma2(hd[px], a2, acc[ocp * 4 + px]);
                }
            }
        }
    }

    // ---- write 8 oc x 4 px ----
    int gy = by * TILE + r, gx = bx * TILE + c;
    float* ob = out + (((size_t)n * (GROUPS * OCG) + g * OCG) * HH + gy) * (size_t)WW + gx;
#pragma unroll
    for (int ocp = 0; ocp < 4; ocp++) {
        float4 lo, hi;
        upk2(acc[ocp * 4 + 0], lo.x, hi.x);
        upk2(acc[ocp * 4 + 1], lo.y, hi.y);
        upk2(acc[ocp * 4 + 2], lo.z, hi.z);
        upk2(acc[ocp * 4 + 3], lo.w, hi.w);
        *(float4*)(ob + (size_t)(2 * ocp)     * HH * WW) = lo;
        *(float4*)(ob + (size_t)(2 * ocp + 1) * HH * WW) = hi;
    }
}

// ---------------------------------------------------------------------------
extern "C" void kernel_launch(void* const* d_in, const int* in_sizes, int n_in,
                              void* d_out, int out_size) {
    const float* data   = (const float*)d_in[0];  // [16,20,384,384]
    const float* alphas = (const float*)d_in[1];  // [5,6,4,8]
    const float* scales = (const float*)d_in[2];  // [5]
    float* out = (float*)d_out;                   // [16,40,384,384]

    make_filters_kernel<<<1, 32>>>(scales);

    dim3 grid(WW / TILE, HH / TILE, NBATCH * GROUPS);  // 12 x 12 x 80
    conv_kernel<<<grid, 256>>>(data, alphas, out);
}

// round 14
// speedup vs baseline: 1.4321x; 1.0908x over previous
#include <cuda_runtime.h>

#define HH 384
#define WW 384
#define NBATCH 16
#define GROUPS 5
#define ICG 4
#define OCG 8
#define KS 5
#define PAD 2
#define TILE 32
#define HALO 36
#define SINX 42   // s_in x-stride: 168B == 8 mod 32 -> conflict-free 4-row LDS.64, >= HALO
#define SHX 44    // s_h  x-stride: 176B == 48 mod 128 -> conflict-free STS.128 phases

typedef unsigned long long u64;

// Dup-packed (v,v) 1D Gaussian-derivative filters: [group][deriv 0..2][tap 0..4]
__device__ u64 g_d2[GROUPS][3][KS];

// ---------------------------------------------------------------------------
__global__ void make_filters_kernel(const float* __restrict__ scales) {
    int s = threadIdx.x;
    if (s >= GROUPS) return;
    const int FS_[5] = {1, 1, 1, 2, 2};
    float mn = 0.2f * s, mx = mn + 0.2f;
    float sigma = (mx - mn) * 0.5f * tanhf(scales[s]) + (mn + mx) * 0.5f;
    int fs = FS_[s], len = 2 * fs + 1;

    float g[5]; float gsum = 0.f;
    for (int k = 0; k < len; k++) {
        float x = (float)(k - fs);
        g[k] = expf(-(x * x) / (2.f * sigma * sigma));
        gsum += g[k];
    }
    float inv = 1.f / gsum;
    const float SQRT2 = 1.4142135623730951f;
    float c1 = -1.f / (sigma * SQRT2);

    float d[3][5];
    for (int i = 0; i < 3; i++)
        for (int k = 0; k < 5; k++) d[i][k] = 0.f;
    int p = (KS - len) / 2;
    for (int k = 0; k < len; k++) {
        float x = (float)(k - fs);
        float u = x / (sigma * SQRT2);
        float gg = g[k] * inv;
        d[0][p + k] = gg;
        d[1][p + k] = c1 * (2.f * u) * gg;
        d[2][p + k] = c1 * c1 * (4.f * u * u - 2.f) * gg;
    }
    for (int i = 0; i < 3; i++)
        for (int k = 0; k < 5; k++) {
            unsigned ui = __float_as_uint(d[i][k]);
            g_d2[s][i][k] = ((u64)ui << 32) | ui;
        }
}

// ---------------------------------------------------------------------------
__device__ __forceinline__ u64 fma2(u64 a, u64 b, u64 c) {
    u64 d;
    asm("fma.rn.f32x2 %0, %1, %2, %3;" : "=l"(d) : "l"(a), "l"(b), "l"(c));
    return d;
}
__device__ __forceinline__ u64 pk2f(float a, float b) {
    u64 r;
    asm("mov.b64 %0, {%1, %2};" : "=l"(r)
        : "r"(__float_as_uint(a)), "r"(__float_as_uint(b)));
    return r;
}
__device__ __forceinline__ u64 dup2(float a) {
    u64 r;
    asm("mov.b64 %0, {%1, %1};" : "=l"(r) : "r"(__float_as_uint(a)));
    return r;
}
__device__ __forceinline__ float2 uview(u64 v) {
    float2 f;
    asm("mov.b64 {%0, %1}, %2;" : "=f"(f.x), "=f"(f.y) : "l"(v));
    return f;
}

// ---------------------------------------------------------------------------
// Fused separable conv:
//   stage 1 (coop):  s_h[j][y][x] = d_j *_x s_in   (per 2-ic batch)
//   stage 2 (thread): vertical d_i *_y s_h[j] + pointwise alpha mix
// Thread owns 2 rows x 1 aligned col-pair = 4 px; acc pairs over oc.
// ---------------------------------------------------------------------------
__global__ __launch_bounds__(256, 3)
void conv_kernel(const float* __restrict__ in,
                 const float* __restrict__ alphas,
                 float* __restrict__ out) {
    __shared__ float s_in[ICG][HALO][SINX];                    // 23.6 KB
    __shared__ __align__(16) float s_h[2][3][HALO][SHX];       // 38.0 KB
    __shared__ float s_a[6 * ICG * OCG];                       // 768 B
    __shared__ __align__(16) u64 s_d[3][8];                    // 192 B

    int bx = blockIdx.x, by = blockIdx.y;
    int n = blockIdx.z / GROUPS;
    int g = blockIdx.z % GROUPS;
    int tid = threadIdx.x;

    if (tid < 192) s_a[tid] = alphas[g * 192 + tid];
    if (tid >= 192 && tid < 192 + 15) {
        int t = tid - 192;
        s_d[t / 5][t % 5] = g_d2[g][t / 5][t % 5];
    }

    // haloed input tile (4 x 36 x 36 values, row stride SINX)
    int y0 = by * TILE - PAD, x0 = bx * TILE - PAD;
    const float* inb = in + ((size_t)n * (GROUPS * ICG) + g * ICG) * (HH * WW);
    for (int i = tid; i < ICG * HALO * HALO; i += 256) {
        int ic  = i / (HALO * HALO);
        int rem = i % (HALO * HALO);
        int yy  = rem / HALO, xx = rem % HALO;
        int gy = y0 + yy, gx = x0 + xx;
        float v = 0.f;
        if (gy >= 0 && gy < HH && gx >= 0 && gx < WW)
            v = inb[(size_t)ic * HH * WW + (size_t)gy * WW + gx];
        s_in[ic][yy][xx] = v;
    }
    __syncthreads();

    int pc = tid & 15;        // pair-col 0..15
    int rp = tid >> 4;        // row-pair 0..15
    int r  = rp * 2;
    int c  = pc * 2;

    u64 d0r[5];
#pragma unroll
    for (int k = 0; k < 5; k++) d0r[k] = s_d[0][k];

    // acc[ocp*4 + px]; px: 0=(r,c) 1=(r,c+1) 2=(r+1,c) 3=(r+1,c+1)
    u64 acc[16];
#pragma unroll
    for (int k = 0; k < 16; k++) acc[k] = 0ull;

    for (int icp = 0; icp < 2; icp++) {
        if (icp) __syncthreads();   // prior s_h fully consumed

        // ---- coop horizontal: 2 ics x 36 rows x 4 chunks of 8 x ----
        for (int s = tid; s < 288; s += 256) {
            int ic2 = s / 144;
            int rem = s - ic2 * 144;
            int y   = rem >> 2;
            int ch  = rem & 3;
            const float* base = &s_in[icp * 2 + ic2][y][ch * 8];

            u64 A[6]; float2 F[6];
#pragma unroll
            for (int k = 0; k < 6; k++) {
                A[k] = *(const u64*)(base + 2 * k);
                F[k] = uview(A[k]);
            }
            u64 S[5];
#pragma unroll
            for (int k = 0; k < 5; k++) S[k] = pk2f(F[k].y, F[k + 1].x);

            float* hrow = &s_h[ic2][0][y][ch * 8];
#pragma unroll
            for (int j = 0; j < 3; j++) {
                ulonglong2 da = *(const ulonglong2*)&s_d[j][0];
                ulonglong2 db = *(const ulonglong2*)&s_d[j][2];
                u64 d4 = s_d[j][4];
                u64 O[4];
#pragma unroll
                for (int k = 0; k < 4; k++) {
                    u64 o = 0ull;
                    o = fma2(A[k],     da.x, o);
                    o = fma2(S[k],     da.y, o);
                    o = fma2(A[k + 1], db.x, o);
                    o = fma2(S[k + 1], db.y, o);
                    o = fma2(A[k + 2], d4,   o);
                    O[k] = o;
                }
                ulonglong2* st = (ulonglong2*)(hrow + j * (HALO * SHX));
                st[0] = make_ulonglong2(O[0], O[1]);
                st[1] = make_ulonglong2(O[2], O[3]);
            }
        }
        __syncthreads();

        // ---- per-thread: vertical + pointwise ----
#pragma unroll
        for (int ic2 = 0; ic2 < 2; ic2++) {
            int ic = icp * 2 + ic2;
#pragma unroll
            for (int j = 0; j < 3; j++) {
                const float* hb = &s_h[ic2][j][r][c];
                u64 rows[6];
#pragma unroll
                for (int k = 0; k < 6; k++)
                    rows[k] = *(const u64*)(hb + k * SHX);
#pragma unroll
                for (int i = 0; i <= 2 - j; i++) {
                    u64 dd[5];
                    if (i == 0) {
#pragma unroll
                        for (int k = 0; k < 5; k++) dd[k] = d0r[k];
                    } else {
                        ulonglong2 da = *(const ulonglong2*)&s_d[i][0];
                        ulonglong2 db = *(const ulonglong2*)&s_d[i][2];
                        dd[0] = da.x; dd[1] = da.y;
                        dd[2] = db.x; dd[3] = db.y;
                        dd[4] = s_d[i][4];
                    }
                    u64 m0 = 0ull, m1 = 0ull;
#pragma unroll
                    for (int k = 0; k < 5; k++) {
                        m0 = fma2(rows[k],     dd[k], m0);
                        m1 = fma2(rows[k + 1], dd[k], m1);
                    }
                    float2 f0 = uview(m0), f1 = uview(m1);
                    u64 h[4] = {dup2(f0.x), dup2(f0.y),
                                dup2(f1.x), dup2(f1.y)};
                    int ij = (i == 0) ? j : ((i == 1) ? 3 + j : 5);
                    const ulonglong2* ap =
                        (const ulonglong2*)&s_a[(ij * ICG + ic) * OCG];
                    ulonglong2 aA = ap[0];
                    ulonglong2 aB = ap[1];
#pragma unroll
                    for (int px = 0; px < 4; px++) {
                        acc[0 * 4 + px] = fma2(h[px], aA.x, acc[0 * 4 + px]);
                        acc[1 * 4 + px] = fma2(h[px], aA.y, acc[1 * 4 + px]);
                        acc[2 * 4 + px] = fma2(h[px], aB.x, acc[2 * 4 + px]);
                        acc[3 * 4 + px] = fma2(h[px], aB.y, acc[3 * 4 + px]);
                    }
                }
            }
        }
    }

    // ---- epilogue: transpose oc-pairs -> col-pairs, 16 STG.64 ----
    int gy = by * TILE + r, gx = bx * TILE + c;
    float* ob = out + (((size_t)n * (GROUPS * OCG) + g * OCG) * HH + gy) * (size_t)WW + gx;
#pragma unroll
    for (int ocp = 0; ocp < 4; ocp++) {
#pragma unroll
        for (int row = 0; row < 2; row++) {
            float2 va = uview(acc[ocp * 4 + row * 2 + 0]);
            float2 vb = uview(acc[ocp * 4 + row * 2 + 1]);
            u64 lo = pk2f(va.x, vb.x);
            u64 hi = pk2f(va.y, vb.y);
            *(u64*)(ob + (size_t)(2 * ocp)     * HH * WW + row * WW) = lo;
            *(u64*)(ob + (size_t)(2 * ocp + 1) * HH * WW + row * WW) = hi;
        }
    }
}

// ---------------------------------------------------------------------------
extern "C" void kernel_launch(void* const* d_in, const int* in_sizes, int n_in,
                              void* d_out, int out_size) {
    const float* data   = (const float*)d_in[0];  // [16,20,384,384]
    const float* alphas = (const float*)d_in[1];  // [5,6,4,8]
    const float* scales = (const float*)d_in[2];  // [5]
    float* out = (float*)d_out;                   // [16,40,384,384]

    make_filters_kernel<<<1, 32>>>(scales);

    dim3 grid(WW / TILE, HH / TILE, NBATCH * GROUPS);  // 12 x 12 x 80
    conv_kernel<<<grid, 256>>>(data, alphas, out);
}